// round 13
// baseline (speedup 1.0000x reference)
#include <cuda_runtime.h>

#define KV 16
#define DIM 15
#define NPIX (2048 * 2048)
#define TPB 128
#define NQUAD (NPIX / 4)
// one thread = 8 pixels: two quads (A, B) NQUAD/2 apart, sharing one k-loop
// so each constant-bank weight fetch feeds 4 FFMA2 chains.

typedef unsigned long long u64;

__device__ __forceinline__ u64 ffma2(u64 a, u64 b, u64 c) {
    u64 d;
    asm("fma.rn.f32x2 %0, %1, %2, %3;" : "=l"(d) : "l"(a), "l"(b), "l"(c));
    return d;
}
__device__ __forceinline__ u64 fadd2(u64 a, u64 b) {
    u64 d;
    asm("add.rn.f32x2 %0, %1, %2;" : "=l"(d) : "l"(a), "l"(b));
    return d;
}
__device__ __forceinline__ u64 pack2(float x, float y) {
    u64 p;
    asm("mov.b64 %0, {%1, %2};" : "=l"(p) : "f"(x), "f"(y));
    return p;
}
__device__ __forceinline__ void unpack2(u64 p, float& x, float& y) {
    asm("mov.b64 {%0, %1}, %2;" : "=f"(x), "=f"(y) : "l"(p));
}

// Embed vertex index k into the low 4 mantissa bits of t (one LOP3), so the
// argmin collapses to a chain of FMNMX. Perturbation <= 16 ulp.
__device__ __forceinline__ float embed_idx(float t, int k) {
    unsigned r;
    asm("lop3.b32 %0, %1, 0xFFFFFFF0, %2, 0xEA;"  // (a & b) | c
        : "=r"(r) : "r"(__float_as_uint(t)), "r"(k));
    return __uint_as_float(r);
}

// Weight layout, per vertex k: 8 ulonglong2.
//   [k][m].x / .y = packed (-2*v[k][2m], dup) / (-2*v[k][2m+1], dup)  for m<7
//   [k][7].x      = packed pair for j=14
//   [k][7].y      = packed (||v_k||^2, ||v_k||^2)
__constant__ ulonglong2 c_wp[KV][8];

// prep writes through the global alias of c_wp; const cache refills per launch.
__global__ void prep_kernel(const float* __restrict__ v, ulonglong2* __restrict__ wp) {
    const int t = threadIdx.x;
    if (t < KV) {
        float b = 0.0f;
        #pragma unroll
        for (int j = 0; j < DIM; ++j) {
            float a = v[t * DIM + j];
            b = fmaf(a, a, b);
        }
        #pragma unroll
        for (int m = 0; m < 7; ++m) {
            float w0 = -2.0f * v[t * DIM + 2 * m];
            float w1 = -2.0f * v[t * DIM + 2 * m + 1];
            wp[t * 8 + m] = make_ulonglong2(pack2(w0, w0), pack2(w1, w1));
        }
        float w14 = -2.0f * v[t * DIM + 14];
        wp[t * 8 + 7] = make_ulonglong2(pack2(w14, w14), pack2(b, b));
    }
}

// t_k = ||v_k||^2 - 2 v_k . z   (monotone in distance; argmin matches)
// dmin = sqrt(max(zz + t_min, 0))

__global__ __launch_bounds__(TPB, 3) void gum_kernel(const float* __restrict__ z,
                                                     float* __restrict__ out) {
    const int t = threadIdx.x;
    const size_t pA = (size_t)blockIdx.x * TPB + t;   // quad A
    const size_t pB = pA + (NQUAD / 2);               // quad B (coalesced stream)
    const u64* zp = (const u64*)z;

    // Front-batch all 30 global loads as LDG.128 (3840 B in flight per warp)
    u64 zloA[DIM], zhiA[DIM], zloB[DIM], zhiB[DIM];
    #pragma unroll
    for (int j = 0; j < DIM; ++j) {
        ulonglong2 a = __ldcs((const ulonglong2*)(zp + (size_t)j * (NPIX / 2) + 2 * pA));
        ulonglong2 b = __ldcs((const ulonglong2*)(zp + (size_t)j * (NPIX / 2) + 2 * pB));
        zloA[j] = a.x; zhiA[j] = a.y;
        zloB[j] = b.x; zhiB[j] = b.y;
    }

    const float FMAX = __int_as_float(0x7f7fffff);
    float bA0 = FMAX, bA1 = FMAX, bA2 = FMAX, bA3 = FMAX;
    float bB0 = FMAX, bB1 = FMAX, bB2 = FMAX, bB3 = FMAX;

    #pragma unroll
    for (int k = 0; k < KV; ++k) {
        // one constant fetch sequence feeds 4 independent FFMA2 chains
        ulonglong2 w7 = c_wp[k][7];
        u64 laA = w7.y, haA = w7.y, laB = w7.y, haB = w7.y;  // ||v_k||^2 pair
        #pragma unroll
        for (int m = 0; m < 7; ++m) {
            ulonglong2 w = c_wp[k][m];
            laA = ffma2(w.x, zloA[2 * m], laA);
            haA = ffma2(w.x, zhiA[2 * m], haA);
            laB = ffma2(w.x, zloB[2 * m], laB);
            haB = ffma2(w.x, zhiB[2 * m], haB);
            laA = ffma2(w.y, zloA[2 * m + 1], laA);
            haA = ffma2(w.y, zhiA[2 * m + 1], haA);
            laB = ffma2(w.y, zloB[2 * m + 1], laB);
            haB = ffma2(w.y, zhiB[2 * m + 1], haB);
        }
        laA = ffma2(w7.x, zloA[14], laA);
        haA = ffma2(w7.x, zhiA[14], haA);
        laB = ffma2(w7.x, zloB[14], laB);
        haB = ffma2(w7.x, zhiB[14], haB);

        float t0, t1, t2, t3;
        unpack2(laA, t0, t1);
        unpack2(haA, t2, t3);
        bA0 = fminf(bA0, embed_idx(t0, k));
        bA1 = fminf(bA1, embed_idx(t1, k));
        bA2 = fminf(bA2, embed_idx(t2, k));
        bA3 = fminf(bA3, embed_idx(t3, k));
        unpack2(laB, t0, t1);
        unpack2(haB, t2, t3);
        bB0 = fminf(bB0, embed_idx(t0, k));
        bB1 = fminf(bB1, embed_idx(t1, k));
        bB2 = fminf(bB2, embed_idx(t2, k));
        bB3 = fminf(bB3, embed_idx(t3, k));
    }

    // ||z||^2 per quad (two split chains each)
    #define ZZ(zlo, zhi, zz0, zz1, zz2, zz3)                       \
    {                                                              \
        u64 za_l = 0ull, zb_l = 0ull, za_h = 0ull, zb_h = 0ull;    \
        _Pragma("unroll")                                          \
        for (int j = 0; j < DIM; j += 2) {                         \
            za_l = ffma2(zlo[j], zlo[j], za_l);                    \
            za_h = ffma2(zhi[j], zhi[j], za_h);                    \
            if (j + 1 < DIM) {                                     \
                zb_l = ffma2(zlo[j + 1], zlo[j + 1], zb_l);        \
                zb_h = ffma2(zhi[j + 1], zhi[j + 1], zb_h);        \
            }                                                      \
        }                                                          \
        unpack2(fadd2(za_l, zb_l), zz0, zz1);                      \
        unpack2(fadd2(za_h, zb_h), zz2, zz3);                      \
    }

    // finalize one quad: winner idx = low 4 bits; masked value = t_min
    #define FINISH(b0, b1, b2, b3, zz0, zz1, zz2, zz3, p)                        \
    {                                                                            \
        unsigned u0 = __float_as_uint(b0), u1 = __float_as_uint(b1);             \
        unsigned u2 = __float_as_uint(b2), u3 = __float_as_uint(b3);             \
        float4 xo = make_float4((float)(u0 & 15u), (float)(u1 & 15u),            \
                                (float)(u2 & 15u), (float)(u3 & 15u));           \
        float m0 = __uint_as_float(u0 & 0xFFFFFFF0u);                            \
        float m1 = __uint_as_float(u1 & 0xFFFFFFF0u);                            \
        float m2 = __uint_as_float(u2 & 0xFFFFFFF0u);                            \
        float m3 = __uint_as_float(u3 & 0xFFFFFFF0u);                            \
        float4 dm = make_float4(sqrtf(fmaxf(zz0 + m0, 0.0f)),                    \
                                sqrtf(fmaxf(zz1 + m1, 0.0f)),                    \
                                sqrtf(fmaxf(zz2 + m2, 0.0f)),                    \
                                sqrtf(fmaxf(zz3 + m3, 0.0f)));                   \
        __stcs((float4*)(out + 4 * (p)), xo);                                    \
        __stcs((float4*)(out + (size_t)NPIX + 4 * (p)), dm);                     \
    }

    {
        float zz0, zz1, zz2, zz3;
        ZZ(zloA, zhiA, zz0, zz1, zz2, zz3)
        FINISH(bA0, bA1, bA2, bA3, zz0, zz1, zz2, zz3, pA)
    }
    {
        float zz0, zz1, zz2, zz3;
        ZZ(zloB, zhiB, zz0, zz1, zz2, zz3)
        FINISH(bB0, bB1, bB2, bB3, zz0, zz1, zz2, zz3, pB)
    }
    #undef ZZ
    #undef FINISH
}

extern "C" void kernel_launch(void* const* d_in, const int* in_sizes, int n_in,
                              void* d_out, int out_size) {
    const float* z = (const float*)d_in[0];  // (15, 2048, 2048) fp32
    const float* v = (const float*)d_in[1];  // (16, 15) fp32
    float* out = (float*)d_out;              // [X (as float) | dmin], each NPIX

    void* wp = nullptr;
    cudaGetSymbolAddress(&wp, c_wp);         // global alias of constant bank
    prep_kernel<<<1, 32>>>(v, (ulonglong2*)wp);

    const int nblocks = NQUAD / (TPB * 2);   // 4096
    gum_kernel<<<nblocks, TPB>>>(z, out);
}